// round 12
// baseline (speedup 1.0000x reference)
#include <cuda_runtime.h>
#include <cuda_fp16.h>
#include <math.h>
#include <stdint.h>

#define B_DIM   4096
#define ZDIM    128
#define IN_DIM  512
#define H_DIM   1024
#define SEQ_LEN 12
#define CAT     (IN_DIM + H_DIM)
#define LDO     (SEQ_LEN * IN_DIM)
#define N12     (2 * H_DIM)

typedef __half  f16;
typedef __half2 f162;

// ---------------- scratch (__device__ globals; no allocs allowed) -----------
__device__ float g_stf[B_DIM * H_DIM];
__device__ float g_spf[B_DIM * H_DIM];
__device__ float g_uf [B_DIM * H_DIM];

__device__ f16 g_tdh[B_DIM * LDO],    g_tdl[B_DIM * LDO];
__device__ f16 g_zh [B_DIM * ZDIM],   g_zl [B_DIM * ZDIM];
__device__ f16 g_sph[B_DIM * H_DIM],  g_spl[B_DIM * H_DIM];
__device__ f16 g_sth[B_DIM * H_DIM],  g_stl[B_DIM * H_DIM];
__device__ f16 g_rsh[B_DIM * H_DIM],  g_rsl[B_DIM * H_DIM];
__device__ f16 g_xh [B_DIM * IN_DIM], g_xl [B_DIM * IN_DIM];

// weights transposed to [N][K] fp16 (hi only — 2-term scheme)
__device__ f16 g_W12h[N12 * CAT];          // W1 rows then W2 rows
__device__ f16 g_W3h [H_DIM * CAT];
__device__ f16 g_Wbh [H_DIM * IN_DIM];
__device__ f16 g_Woh [IN_DIM * H_DIM];
__device__ f16 g_Wzh [IN_DIM * ZDIM];

enum { EPI_LIN = 0, EPI_BELTA = 1, EPI_SIGUR = 2, EPI_NEW = 3 };

// ---------------- prep kernels ---------------------------------------------
__global__ void zero_kernel(float* __restrict__ p, int n) {
    int i = blockIdx.x * blockDim.x + threadIdx.x;
    if (i < n) p[i] = 0.0f;
}

__global__ void asplit(const float* __restrict__ X, int n4,
                       f16* __restrict__ H, f16* __restrict__ L) {
    int i = blockIdx.x * blockDim.x + threadIdx.x;
    if (i >= n4) return;
    float4 v = ((const float4*)X)[i];
    f16 h0 = __float2half_rn(v.x), h1 = __float2half_rn(v.y);
    f16 h2 = __float2half_rn(v.z), h3 = __float2half_rn(v.w);
    f162 H0; H0.x = h0; H0.y = h1;
    f162 H1; H1.x = h2; H1.y = h3;
    f162 L0, L1;
    L0.x = __float2half_rn(v.x - __half2float(h0));
    L0.y = __float2half_rn(v.y - __half2float(h1));
    L1.x = __float2half_rn(v.z - __half2float(h2));
    L1.y = __float2half_rn(v.w - __half2float(h3));
    ((f162*)H)[2 * i] = H0; ((f162*)H)[2 * i + 1] = H1;
    ((f162*)L)[2 * i] = L0; ((f162*)L)[2 * i + 1] = L1;
}

__global__ void whalf(const float* __restrict__ W, int K, int N,
                      f16* __restrict__ Th) {
    __shared__ float t[32][33];
    const int n0 = blockIdx.x * 32, k0 = blockIdx.y * 32;
    const int tx = threadIdx.x, ty = threadIdx.y;   // (32, 8)
#pragma unroll
    for (int j = 0; j < 32; j += 8)
        t[ty + j][tx] = W[(size_t)(k0 + ty + j) * N + (n0 + tx)];
    __syncthreads();
#pragma unroll
    for (int j = 0; j < 32; j += 8)
        Th[(size_t)(n0 + ty + j) * K + (k0 + tx)] = __float2half_rn(t[tx][ty + j]);
}

// ---------------- PTX primitives --------------------------------------------
__device__ __forceinline__ uint32_t smem_u32(const void* p) {
    uint32_t a;
    asm("{ .reg .u64 t; cvta.to.shared.u64 t, %1; cvt.u32.u64 %0, t; }" : "=r"(a) : "l"(p));
    return a;
}

#define CP16(dst, src) \
    asm volatile("cp.async.ca.shared.global [%0], [%1], 16;" :: "r"(dst), "l"(src) : "memory")
#define CPCOMMIT() asm volatile("cp.async.commit_group;" ::: "memory")
#define CPWAIT1()  asm volatile("cp.async.wait_group 1;"  ::: "memory")

#define LDSM4(r, a) \
    asm volatile("ldmatrix.sync.aligned.m8n8.x4.shared.b16 {%0,%1,%2,%3}, [%4];" \
        : "=r"((r)[0]), "=r"((r)[1]), "=r"((r)[2]), "=r"((r)[3]) : "r"(a))

#define MMA(c, a, b0, b1) \
    asm volatile("mma.sync.aligned.m16n8k16.row.col.f32.f16.f16.f32 " \
        "{%0,%1,%2,%3}, {%4,%5,%6,%7}, {%8,%9}, {%0,%1,%2,%3};" \
        : "+f"((c)[0]), "+f"((c)[1]), "+f"((c)[2]), "+f"((c)[3]) \
        : "r"((a)[0]), "r"((a)[1]), "r"((a)[2]), "r"((a)[3]), "r"(b0), "r"(b1))

// ---------------- HMMA GEMM body (R7 core, unchanged math) ------------------
#define KC      32
#define AROW80  80
#define TILE_B  (128 * AROW80)           // 10240 B
#define STAGE   (3 * TILE_B)             // Ahi, Alo, Bhi
#define NSTG    3
#define SMEM_T  (NSTG * STAGE)           // 92160 B

template <int EPI>
__device__ __forceinline__ void gemm_body(
    int bm, int bn,
    const f16* __restrict__ Ah1, const f16* __restrict__ Al1, int lda1, int K1,
    const f16* __restrict__ Ah2, const f16* __restrict__ Al2, int lda2, int K2,
    const f16* __restrict__ Bh,
    const float* __restrict__ bias, const float* __restrict__ bias2,
    const float* __restrict__ ex1, const float* __restrict__ ex2,
    float* __restrict__ Cf, int ldcf,
    f16* __restrict__ Ch, f16* __restrict__ Cl, int ldch)
{
    extern __shared__ __align__(128) char smem[];
    const uint32_t sb = smem_u32(smem);
    const int tid = threadIdx.x;
    const int Ktot = K1 + K2;
    const int KT = Ktot / KC;

    const int cr = tid >> 1;
    const int cs = (tid & 1) * 2;

    auto issue = [&](int c, int s) {
        const int ks = c * KC;
        const f16 *ah, *al;
        if (ks < K1) {
            ah = Ah1 + (size_t)(bm + cr) * lda1 + ks;
            al = Al1 + (size_t)(bm + cr) * lda1 + ks;
        } else {
            ah = Ah2 + (size_t)(bm + cr) * lda2 + (ks - K1);
            al = Al2 + (size_t)(bm + cr) * lda2 + (ks - K1);
        }
        const f16* bh = Bh + (size_t)(bn + cr) * Ktot + ks;
        const uint32_t base = sb + (uint32_t)s * STAGE + (uint32_t)cr * AROW80;
#pragma unroll
        for (int g = 0; g < 2; g++) {
            const int seg = cs + g;
            const uint32_t off = (uint32_t)seg * 16u;
            CP16(base + 0 * TILE_B + off, ah + seg * 8);
            CP16(base + 1 * TILE_B + off, al + seg * 8);
            CP16(base + 2 * TILE_B + off, bh + seg * 8);
        }
    };

    const int warp = tid >> 5, lane = tid & 31;
    const int wm = (warp & 3) * 32;
    const int wn = (warp >> 2) * 64;
    const int lr = lane & 7;
    const uint32_t aBase = (uint32_t)(wm + lr + ((lane >> 3) & 1) * 8) * AROW80
                         + (uint32_t)(((lane >> 4) & 1) * 8) * 2;
    const uint32_t bBase = (uint32_t)(wn + lr + ((lane >> 4) & 1) * 8) * AROW80
                         + (uint32_t)(((lane >> 3) & 1) * 8) * 2;

    float acc[2][8][4];
#pragma unroll
    for (int mi = 0; mi < 2; mi++)
#pragma unroll
        for (int j = 0; j < 8; j++)
#pragma unroll
            for (int q = 0; q < 4; q++) acc[mi][j][q] = 0.0f;

    issue(0, 0); CPCOMMIT();
    issue(1, 1); CPCOMMIT();

    for (int c = 0; c < KT; c++) {
        CPWAIT1();
        __syncthreads();
        if (c + 2 < KT) issue(c + 2, (c + 2) % NSTG);
        CPCOMMIT();
        const uint32_t st = sb + (uint32_t)(c % NSTG) * STAGE;
#pragma unroll
        for (int k2 = 0; k2 < 2; k2++) {
            uint32_t ah[2][4], al[2][4];
#pragma unroll
            for (int mi = 0; mi < 2; mi++) {
                const uint32_t ao = st + aBase + (uint32_t)mi * (16 * AROW80)
                                  + (uint32_t)k2 * 32;
                LDSM4(ah[mi], ao);
                LDSM4(al[mi], ao + TILE_B);
            }
#pragma unroll
            for (int jj = 0; jj < 4; jj++) {
                uint32_t b4[4];
                const uint32_t bo = st + 2 * TILE_B + bBase
                                  + (uint32_t)jj * (16 * AROW80) + (uint32_t)k2 * 32;
                LDSM4(b4, bo);
                MMA(acc[0][2 * jj],     ah[0], b4[0], b4[1]);
                MMA(acc[1][2 * jj],     ah[1], b4[0], b4[1]);
                MMA(acc[0][2 * jj],     al[0], b4[0], b4[1]);
                MMA(acc[1][2 * jj],     al[1], b4[0], b4[1]);
                MMA(acc[0][2 * jj + 1], ah[0], b4[2], b4[3]);
                MMA(acc[1][2 * jj + 1], ah[1], b4[2], b4[3]);
                MMA(acc[0][2 * jj + 1], al[0], b4[2], b4[3]);
                MMA(acc[1][2 * jj + 1], al[1], b4[2], b4[3]);
            }
        }
    }

    // --- epilogue ---
    const int r0 = bm + wm + (lane >> 2);
    const int c0 = bn + wn + 2 * (lane & 3);

    auto split2 = [&](f16* Hp, f16* Lp, size_t off, float v0, float v1) {
        f16 h0 = __float2half_rn(v0), h1 = __float2half_rn(v1);
        f162 hh; hh.x = h0; hh.y = h1;
        f162 ll;
        ll.x = __float2half_rn(v0 - __half2float(h0));
        ll.y = __float2half_rn(v1 - __half2float(h1));
        *(f162*)(Hp + off) = hh;
        *(f162*)(Lp + off) = ll;
    };

    auto dopair = [&](int row, int col, float v0, float v1) {
        if (EPI == EPI_SIGUR) {
            if (col < H_DIM) {
                float2 bs = *(const float2*)(bias + col);
                v0 = 1.0f / (1.0f + __expf(-(v0 + bs.x)));
                v1 = 1.0f / (1.0f + __expf(-(v1 + bs.y)));
                *(float2*)(Cf + (size_t)row * ldcf + col) = make_float2(v0, v1);
            } else {
                const int cc = col - H_DIM;
                float2 bs = *(const float2*)(bias2 + cc);
                float2 e  = *(const float2*)(ex1 + (size_t)row * H_DIM + cc);
                v0 = e.x / (1.0f + __expf(-(v0 + bs.x)));
                v1 = e.y / (1.0f + __expf(-(v1 + bs.y)));
                split2(Ch, Cl, (size_t)row * ldch + cc, v0, v1);
            }
            return;
        }
        float2 bs = *(const float2*)(bias + col);
        v0 += bs.x; v1 += bs.y;
        if (EPI == EPI_BELTA) {
            float2 e = *(const float2*)(ex1 + (size_t)row * H_DIM + col);
            v0 = __expf(-fmaxf(v0, 0.0f)) * e.x;
            v1 = __expf(-fmaxf(v1, 0.0f)) * e.y;
        } else if (EPI == EPI_NEW) {
            float2 eu = *(const float2*)(ex1 + (size_t)row * H_DIM + col);
            float2 es = *(const float2*)(ex2 + (size_t)row * H_DIM + col);
            v0 = (1.0f - eu.x) * es.x + eu.x * tanhf(v0);
            v1 = (1.0f - eu.y) * es.y + eu.y * tanhf(v1);
        }
        if (Cf) *(float2*)(Cf + (size_t)row * ldcf + col) = make_float2(v0, v1);
        if (Ch) split2(Ch, Cl, (size_t)row * ldch + col, v0, v1);
    };

#pragma unroll
    for (int mi = 0; mi < 2; mi++)
#pragma unroll
        for (int j = 0; j < 8; j++) {
            const int row = r0 + mi * 16;
            const int col = c0 + j * 8;
            dopair(row,     col, acc[mi][j][0], acc[mi][j][1]);
            dopair(row + 8, col, acc[mi][j][2], acc[mi][j][3]);
        }
}

// ---------------- kernel wrappers -------------------------------------------
template <int EPI>
__global__ __launch_bounds__(256, 2)
void tgemm(const f16* __restrict__ Ah1, const f16* __restrict__ Al1, int lda1, int K1,
           const f16* __restrict__ Ah2, const f16* __restrict__ Al2, int lda2, int K2,
           const f16* __restrict__ Bh,
           const float* __restrict__ bias, const float* __restrict__ bias2,
           const float* __restrict__ ex1, const float* __restrict__ ex2,
           float* __restrict__ Cf, int ldcf,
           f16* __restrict__ Ch, f16* __restrict__ Cl, int ldch)
{
    gemm_body<EPI>(blockIdx.y * 128, blockIdx.x * 128,
                   Ah1, Al1, lda1, K1, Ah2, Al2, lda2, K2,
                   Bh, bias, bias2, ex1, ex2, Cf, ldcf, Ch, Cl, ldch);
}

// Fused launch: CTAs [0,256) run BELTA(t); CTAs [256,384) run an EPI_LIN GEMM
// (OUT(t-1) in steady state, or X0 for the prologue call).
__global__ __launch_bounds__(256, 2)
void fused_ob(const f16* __restrict__ btdh, const f16* __restrict__ btdl,
              const f16* __restrict__ Wbh, const float* __restrict__ b_belta,
              const float* __restrict__ stf,
              float* __restrict__ spf, f16* __restrict__ sph, f16* __restrict__ spl,
              const f16* __restrict__ oAh, const f16* __restrict__ oAl,
              int olda, int oK,
              const f16* __restrict__ oB, const float* __restrict__ obias,
              float* __restrict__ oCf, int oldcf,
              f16* __restrict__ oCh, f16* __restrict__ oCl, int oldch)
{
    const int idx = blockIdx.x;
    if (idx < 256) {
        gemm_body<EPI_BELTA>((idx >> 3) * 128, (idx & 7) * 128,
                             btdh, btdl, LDO, IN_DIM,
                             nullptr, nullptr, 0, 0,
                             Wbh, b_belta, nullptr, stf, nullptr,
                             spf, H_DIM, sph, spl, H_DIM);
    } else {
        const int j = idx - 256;
        gemm_body<EPI_LIN>((j >> 2) * 128, (j & 3) * 128,
                           oAh, oAl, olda, oK,
                           nullptr, nullptr, 0, 0,
                           oB, obias, nullptr, nullptr, nullptr,
                           oCf, oldcf, oCh, oCl, oldch);
    }
}

// ---------------- host -------------------------------------------------------
extern "C" void kernel_launch(void* const* d_in, const int* in_sizes, int n_in,
                              void* d_out, int out_size)
{
    const float* z       = (const float*)d_in[0];
    const float* td      = (const float*)d_in[1];
    const float* W_belta = (const float*)d_in[2];
    const float* b_belta = (const float*)d_in[3];
    const float* W_z     = (const float*)d_in[4];
    const float* b_z     = (const float*)d_in[5];
    const float* W1      = (const float*)d_in[6];
    const float* b1      = (const float*)d_in[7];
    const float* W2      = (const float*)d_in[8];
    const float* b2      = (const float*)d_in[9];
    const float* W3      = (const float*)d_in[10];
    const float* b3      = (const float*)d_in[11];
    const float* W_out   = (const float*)d_in[12];
    const float* b_out   = (const float*)d_in[13];
    float* out = (float*)d_out;

    float *stf, *spf, *uf;
    cudaGetSymbolAddress((void**)&stf, g_stf);
    cudaGetSymbolAddress((void**)&spf, g_spf);
    cudaGetSymbolAddress((void**)&uf,  g_uf);

    f16 *tdh, *tdl, *zh, *zl, *sph, *spl, *sth, *stl, *rsh, *rsl, *xh, *xl;
    cudaGetSymbolAddress((void**)&tdh, g_tdh); cudaGetSymbolAddress((void**)&tdl, g_tdl);
    cudaGetSymbolAddress((void**)&zh,  g_zh);  cudaGetSymbolAddress((void**)&zl,  g_zl);
    cudaGetSymbolAddress((void**)&sph, g_sph); cudaGetSymbolAddress((void**)&spl, g_spl);
    cudaGetSymbolAddress((void**)&sth, g_sth); cudaGetSymbolAddress((void**)&stl, g_stl);
    cudaGetSymbolAddress((void**)&rsh, g_rsh); cudaGetSymbolAddress((void**)&rsl, g_rsl);
    cudaGetSymbolAddress((void**)&xh,  g_xh);  cudaGetSymbolAddress((void**)&xl,  g_xl);

    f16 *W12h, *W3h, *Wbh, *Woh, *Wzh;
    cudaGetSymbolAddress((void**)&W12h, g_W12h);
    cudaGetSymbolAddress((void**)&W3h,  g_W3h);
    cudaGetSymbolAddress((void**)&Wbh,  g_Wbh);
    cudaGetSymbolAddress((void**)&Woh,  g_Woh);
    cudaGetSymbolAddress((void**)&Wzh,  g_Wzh);

    cudaFuncSetAttribute(tgemm<EPI_LIN>,   cudaFuncAttributeMaxDynamicSharedMemorySize, SMEM_T);
    cudaFuncSetAttribute(tgemm<EPI_SIGUR>, cudaFuncAttributeMaxDynamicSharedMemorySize, SMEM_T);
    cudaFuncSetAttribute(tgemm<EPI_NEW>,   cudaFuncAttributeMaxDynamicSharedMemorySize, SMEM_T);
    cudaFuncSetAttribute(fused_ob,         cudaFuncAttributeMaxDynamicSharedMemorySize, SMEM_T);

    // ---- per-launch prep (deterministic for graph replay) ----
    zero_kernel<<<(B_DIM * H_DIM + 1023) / 1024, 1024>>>(stf, B_DIM * H_DIM);
    {
        int n4 = (B_DIM * LDO) / 4;
        asplit<<<(n4 + 255) / 256, 256>>>(td, n4, tdh, tdl);
        n4 = (B_DIM * ZDIM) / 4;
        asplit<<<(n4 + 255) / 256, 256>>>(z, n4, zh, zl);
    }
    dim3 tb(32, 8);
    whalf<<<dim3(H_DIM / 32, CAT / 32),    tb>>>(W1,      CAT,    H_DIM,  W12h);
    whalf<<<dim3(H_DIM / 32, CAT / 32),    tb>>>(W2,      CAT,    H_DIM,  W12h + (size_t)H_DIM * CAT);
    whalf<<<dim3(H_DIM / 32, CAT / 32),    tb>>>(W3,      CAT,    H_DIM,  W3h);
    whalf<<<dim3(H_DIM / 32, IN_DIM / 32), tb>>>(W_belta, IN_DIM, H_DIM,  Wbh);
    whalf<<<dim3(IN_DIM / 32, H_DIM / 32), tb>>>(W_out,   H_DIM,  IN_DIM, Woh);
    whalf<<<dim3(IN_DIM / 32, ZDIM / 32),  tb>>>(W_z,     ZDIM,   IN_DIM, Wzh);

    const dim3 blk(256);
    const dim3 gridH (H_DIM / 128,  B_DIM / 128);   // (8, 32)  NEW
    const dim3 gridH2(N12 / 128,    B_DIM / 128);   // (16, 32) SIGUR
    const dim3 gridI (IN_DIM / 128, B_DIM / 128);   // (4, 32)  final OUT

    // prologue fused: BELTA(0) [state=0 -> spre=0 anyway, but computed] + X0
    fused_ob<<<384, blk, SMEM_T>>>(tdh, tdl, Wbh, b_belta, stf,
                                   spf, sph, spl,
                                   zh, zl, ZDIM, ZDIM, Wzh, b_z,
                                   nullptr, 0, xh, xl, IN_DIM);

    for (int t = 0; t < SEQ_LEN; t++) {
        // fused: u = sig([spre|x]W1+b1) -> uf ;  rs = sig([spre|x]W2+b2)*spre -> hi/lo
        tgemm<EPI_SIGUR><<<gridH2, blk, SMEM_T>>>(sph, spl, H_DIM, H_DIM,
                                                  xh, xl, IN_DIM, IN_DIM,
                                                  W12h, b1, b2, spf, nullptr,
                                                  uf, H_DIM, rsh, rsl, H_DIM);
        // state = (1-u)*spre + u*tanh([rs|x] @ W3 + b3)
        tgemm<EPI_NEW><<<gridH, blk, SMEM_T>>>(rsh, rsl, H_DIM, H_DIM,
                                               xh, xl, IN_DIM, IN_DIM,
                                               W3h, b3, nullptr, uf, spf,
                                               stf, H_DIM, sth, stl, H_DIM);
        if (t + 1 < SEQ_LEN) {
            // fused: BELTA(t+1) (reads stf) + OUT(t) (reads sth/stl, writes out + x)
            fused_ob<<<384, blk, SMEM_T>>>(tdh + (size_t)(t + 1) * IN_DIM,
                                           tdl + (size_t)(t + 1) * IN_DIM,
                                           Wbh, b_belta, stf,
                                           spf, sph, spl,
                                           sth, stl, H_DIM, H_DIM, Woh, b_out,
                                           out + (size_t)t * IN_DIM, LDO,
                                           xh, xl, IN_DIM);
        }
    }

    // final out_11 = state @ W_out + b_out (no x feedback needed)
    tgemm<EPI_LIN><<<gridI, blk, SMEM_T>>>(sth, stl, H_DIM, H_DIM,
                                           nullptr, nullptr, 0, 0,
                                           Woh, b_out, nullptr, nullptr, nullptr,
                                           out + (size_t)(SEQ_LEN - 1) * IN_DIM, LDO,
                                           nullptr, nullptr, 0);
}

// round 13
// speedup vs baseline: 1.6832x; 1.6832x over previous
#include <cuda_runtime.h>
#include <cuda_fp16.h>
#include <math.h>
#include <stdint.h>

#define B_DIM   4096
#define ZDIM    128
#define IN_DIM  512
#define H_DIM   1024
#define SEQ_LEN 12
#define CAT     (IN_DIM + H_DIM)
#define LDO     (SEQ_LEN * IN_DIM)
#define N12     (2 * H_DIM)

typedef __half  f16;
typedef __half2 f162;

// ---------------- scratch (__device__ globals; no allocs allowed) -----------
__device__ float g_stf[B_DIM * H_DIM];
__device__ float g_spf[B_DIM * H_DIM];
__device__ float g_uf [B_DIM * H_DIM];

__device__ f16 g_tdh[B_DIM * LDO];
__device__ f16 g_zh [B_DIM * ZDIM];
__device__ f16 g_sph[B_DIM * H_DIM];
__device__ f16 g_sth[B_DIM * H_DIM];
__device__ f16 g_rsh[B_DIM * H_DIM];
__device__ f16 g_xh [B_DIM * IN_DIM];

// weights transposed to [N][K] fp16
__device__ f16 g_W12h[N12 * CAT];          // W1 rows then W2 rows
__device__ f16 g_W3h [H_DIM * CAT];
__device__ f16 g_Wbh [H_DIM * IN_DIM];
__device__ f16 g_Woh [IN_DIM * H_DIM];
__device__ f16 g_Wzh [IN_DIM * ZDIM];

enum { EPI_LIN = 0, EPI_BELTA = 1, EPI_SIGUR = 2, EPI_NEW = 3 };

// ---------------- prep kernels ---------------------------------------------
__global__ void zero_kernel(float* __restrict__ p, int n) {
    int i = blockIdx.x * blockDim.x + threadIdx.x;
    if (i < n) p[i] = 0.0f;
}

// fp32 -> fp16 round (contiguous)
__global__ void ahalf(const float* __restrict__ X, int n4, f16* __restrict__ H) {
    int i = blockIdx.x * blockDim.x + threadIdx.x;
    if (i >= n4) return;
    float4 v = ((const float4*)X)[i];
    ((f162*)H)[2 * i]     = __floats2half2_rn(v.x, v.y);
    ((f162*)H)[2 * i + 1] = __floats2half2_rn(v.z, v.w);
}

// transpose + fp16 round: W (K,N) row-major -> Th [N][K]
__global__ void whalf(const float* __restrict__ W, int K, int N,
                      f16* __restrict__ Th) {
    __shared__ float t[32][33];
    const int n0 = blockIdx.x * 32, k0 = blockIdx.y * 32;
    const int tx = threadIdx.x, ty = threadIdx.y;   // (32, 8)
#pragma unroll
    for (int j = 0; j < 32; j += 8)
        t[ty + j][tx] = W[(size_t)(k0 + ty + j) * N + (n0 + tx)];
    __syncthreads();
#pragma unroll
    for (int j = 0; j < 32; j += 8)
        Th[(size_t)(n0 + ty + j) * K + (k0 + tx)] = __float2half_rn(t[tx][ty + j]);
}

// ---------------- PTX primitives --------------------------------------------
__device__ __forceinline__ uint32_t smem_u32(const void* p) {
    uint32_t a;
    asm("{ .reg .u64 t; cvta.to.shared.u64 t, %1; cvt.u32.u64 %0, t; }" : "=r"(a) : "l"(p));
    return a;
}

#define CP16(dst, src) \
    asm volatile("cp.async.ca.shared.global [%0], [%1], 16;" :: "r"(dst), "l"(src) : "memory")
#define CPCOMMIT() asm volatile("cp.async.commit_group;" ::: "memory")
#define CPWAIT1()  asm volatile("cp.async.wait_group 1;"  ::: "memory")

#define LDSM4(r, a) \
    asm volatile("ldmatrix.sync.aligned.m8n8.x4.shared.b16 {%0,%1,%2,%3}, [%4];" \
        : "=r"((r)[0]), "=r"((r)[1]), "=r"((r)[2]), "=r"((r)[3]) : "r"(a))

#define MMA(c, a, b0, b1) \
    asm volatile("mma.sync.aligned.m16n8k16.row.col.f32.f16.f16.f32 " \
        "{%0,%1,%2,%3}, {%4,%5,%6,%7}, {%8,%9}, {%0,%1,%2,%3};" \
        : "+f"((c)[0]), "+f"((c)[1]), "+f"((c)[2]), "+f"((c)[3]) \
        : "r"((a)[0]), "r"((a)[1]), "r"((a)[2]), "r"((a)[3]), "r"(b0), "r"(b1))

// ---------------- HMMA GEMM with fused epilogue -----------------------------
// CTA 128x128, 8 warps = 4(M) x 2(N), warp tile 32x64, occ 2 (R7 layout),
// pure fp16 operands (no lo-term).
#define KC      32
#define AROW80  80
#define TILE_B  (128 * AROW80)           // 10240 B
#define STAGE   (2 * TILE_B)             // A, B = 20480 B
#define NSTG    3
#define SMEM_T  (NSTG * STAGE)           // 61440 B

template <int EPI>
__global__ __launch_bounds__(256, 2)
void tgemm(const f16* __restrict__ Ah1, int lda1, int K1,
           const f16* __restrict__ Ah2, int lda2, int K2,
           const f16* __restrict__ Bh,
           const float* __restrict__ bias, const float* __restrict__ bias2,
           const float* __restrict__ ex1, const float* __restrict__ ex2,
           float* __restrict__ Cf, int ldcf,
           f16* __restrict__ Ch, int ldch)
{
    extern __shared__ __align__(128) char smem[];
    const uint32_t sb = smem_u32(smem);
    const int tid = threadIdx.x;
    const int bm = blockIdx.y * 128, bn = blockIdx.x * 128;
    const int Ktot = K1 + K2;
    const int KT = Ktot / KC;

    const int cr = tid >> 1;
    const int cs = (tid & 1) * 2;

    auto issue = [&](int c, int s) {
        const int ks = c * KC;
        const f16* ah = (ks < K1)
            ? Ah1 + (size_t)(bm + cr) * lda1 + ks
            : Ah2 + (size_t)(bm + cr) * lda2 + (ks - K1);
        const f16* bh = Bh + (size_t)(bn + cr) * Ktot + ks;
        const uint32_t base = sb + (uint32_t)s * STAGE + (uint32_t)cr * AROW80;
#pragma unroll
        for (int g = 0; g < 2; g++) {
            const int seg = cs + g;
            const uint32_t off = (uint32_t)seg * 16u;
            CP16(base + off,          ah + seg * 8);
            CP16(base + TILE_B + off, bh + seg * 8);
        }
    };

    const int warp = tid >> 5, lane = tid & 31;
    const int wm = (warp & 3) * 32;
    const int wn = (warp >> 2) * 64;
    const int lr = lane & 7;
    const uint32_t aBase = (uint32_t)(wm + lr + ((lane >> 3) & 1) * 8) * AROW80
                         + (uint32_t)(((lane >> 4) & 1) * 8) * 2;
    const uint32_t bBase = (uint32_t)(wn + lr + ((lane >> 4) & 1) * 8) * AROW80
                         + (uint32_t)(((lane >> 3) & 1) * 8) * 2;

    float acc[2][8][4];
#pragma unroll
    for (int mi = 0; mi < 2; mi++)
#pragma unroll
        for (int j = 0; j < 8; j++)
#pragma unroll
            for (int q = 0; q < 4; q++) acc[mi][j][q] = 0.0f;

    issue(0, 0); CPCOMMIT();
    issue(1, 1); CPCOMMIT();

    for (int c = 0; c < KT; c++) {
        CPWAIT1();
        __syncthreads();
        if (c + 2 < KT) issue(c + 2, (c + 2) % NSTG);
        CPCOMMIT();
        const uint32_t st = sb + (uint32_t)(c % NSTG) * STAGE;
#pragma unroll
        for (int k2 = 0; k2 < 2; k2++) {
            uint32_t ah[2][4];
#pragma unroll
            for (int mi = 0; mi < 2; mi++)
                LDSM4(ah[mi], st + aBase + (uint32_t)mi * (16 * AROW80)
                              + (uint32_t)k2 * 32);
#pragma unroll
            for (int jj = 0; jj < 4; jj++) {
                uint32_t b4[4];
                const uint32_t bo = st + TILE_B + bBase
                                  + (uint32_t)jj * (16 * AROW80) + (uint32_t)k2 * 32;
                LDSM4(b4, bo);
                MMA(acc[0][2 * jj],     ah[0], b4[0], b4[1]);
                MMA(acc[1][2 * jj],     ah[1], b4[0], b4[1]);
                MMA(acc[0][2 * jj + 1], ah[0], b4[2], b4[3]);
                MMA(acc[1][2 * jj + 1], ah[1], b4[2], b4[3]);
            }
        }
    }

    // --- epilogue ---
    const int r0 = bm + wm + (lane >> 2);
    const int c0 = bn + wn + 2 * (lane & 3);

    auto dopair = [&](int row, int col, float v0, float v1) {
        if (EPI == EPI_SIGUR) {
            if (col < H_DIM) {
                float2 bs = *(const float2*)(bias + col);
                v0 = 1.0f / (1.0f + __expf(-(v0 + bs.x)));
                v1 = 1.0f / (1.0f + __expf(-(v1 + bs.y)));
                *(float2*)(Cf + (size_t)row * ldcf + col) = make_float2(v0, v1);
            } else {
                const int cc = col - H_DIM;
                float2 bs = *(const float2*)(bias2 + cc);
                float2 e  = *(const float2*)(ex1 + (size_t)row * H_DIM + cc);
                v0 = e.x / (1.0f + __expf(-(v0 + bs.x)));
                v1 = e.y / (1.0f + __expf(-(v1 + bs.y)));
                *(f162*)(Ch + (size_t)row * ldch + cc) = __floats2half2_rn(v0, v1);
            }
            return;
        }
        float2 bs = *(const float2*)(bias + col);
        v0 += bs.x; v1 += bs.y;
        if (EPI == EPI_BELTA) {
            float2 e = *(const float2*)(ex1 + (size_t)row * H_DIM + col);
            v0 = __expf(-fmaxf(v0, 0.0f)) * e.x;
            v1 = __expf(-fmaxf(v1, 0.0f)) * e.y;
        } else if (EPI == EPI_NEW) {
            float2 eu = *(const float2*)(ex1 + (size_t)row * H_DIM + col);
            float2 es = *(const float2*)(ex2 + (size_t)row * H_DIM + col);
            v0 = (1.0f - eu.x) * es.x + eu.x * tanhf(v0);
            v1 = (1.0f - eu.y) * es.y + eu.y * tanhf(v1);
        }
        if (Cf) *(float2*)(Cf + (size_t)row * ldcf + col) = make_float2(v0, v1);
        if (Ch) *(f162*)(Ch + (size_t)row * ldch + col) = __floats2half2_rn(v0, v1);
    };

#pragma unroll
    for (int mi = 0; mi < 2; mi++)
#pragma unroll
        for (int j = 0; j < 8; j++) {
            const int row = r0 + mi * 16;
            const int col = c0 + j * 8;
            dopair(row,     col, acc[mi][j][0], acc[mi][j][1]);
            dopair(row + 8, col, acc[mi][j][2], acc[mi][j][3]);
        }
}

// ---------------- host -------------------------------------------------------
extern "C" void kernel_launch(void* const* d_in, const int* in_sizes, int n_in,
                              void* d_out, int out_size)
{
    const float* z       = (const float*)d_in[0];
    const float* td      = (const float*)d_in[1];
    const float* W_belta = (const float*)d_in[2];
    const float* b_belta = (const float*)d_in[3];
    const float* W_z     = (const float*)d_in[4];
    const float* b_z     = (const float*)d_in[5];
    const float* W1      = (const float*)d_in[6];
    const float* b1      = (const float*)d_in[7];
    const float* W2      = (const float*)d_in[8];
    const float* b2      = (const float*)d_in[9];
    const float* W3      = (const float*)d_in[10];
    const float* b3      = (const float*)d_in[11];
    const float* W_out   = (const float*)d_in[12];
    const float* b_out   = (const float*)d_in[13];
    float* out = (float*)d_out;

    float *stf, *spf, *uf;
    cudaGetSymbolAddress((void**)&stf, g_stf);
    cudaGetSymbolAddress((void**)&spf, g_spf);
    cudaGetSymbolAddress((void**)&uf,  g_uf);

    f16 *tdh, *zh, *sph, *sth, *rsh, *xh;
    cudaGetSymbolAddress((void**)&tdh, g_tdh);
    cudaGetSymbolAddress((void**)&zh,  g_zh);
    cudaGetSymbolAddress((void**)&sph, g_sph);
    cudaGetSymbolAddress((void**)&sth, g_sth);
    cudaGetSymbolAddress((void**)&rsh, g_rsh);
    cudaGetSymbolAddress((void**)&xh,  g_xh);

    f16 *W12h, *W3h, *Wbh, *Woh, *Wzh;
    cudaGetSymbolAddress((void**)&W12h, g_W12h);
    cudaGetSymbolAddress((void**)&W3h,  g_W3h);
    cudaGetSymbolAddress((void**)&Wbh,  g_Wbh);
    cudaGetSymbolAddress((void**)&Woh,  g_Woh);
    cudaGetSymbolAddress((void**)&Wzh,  g_Wzh);

    cudaFuncSetAttribute(tgemm<EPI_LIN>,   cudaFuncAttributeMaxDynamicSharedMemorySize, SMEM_T);
    cudaFuncSetAttribute(tgemm<EPI_BELTA>, cudaFuncAttributeMaxDynamicSharedMemorySize, SMEM_T);
    cudaFuncSetAttribute(tgemm<EPI_SIGUR>, cudaFuncAttributeMaxDynamicSharedMemorySize, SMEM_T);
    cudaFuncSetAttribute(tgemm<EPI_NEW>,   cudaFuncAttributeMaxDynamicSharedMemorySize, SMEM_T);

    // ---- per-launch prep (deterministic for graph replay) ----
    zero_kernel<<<(B_DIM * H_DIM + 1023) / 1024, 1024>>>(stf, B_DIM * H_DIM);
    {
        int n4 = (B_DIM * LDO) / 4;
        ahalf<<<(n4 + 255) / 256, 256>>>(td, n4, tdh);
        n4 = (B_DIM * ZDIM) / 4;
        ahalf<<<(n4 + 255) / 256, 256>>>(z, n4, zh);
    }
    dim3 tb(32, 8);
    whalf<<<dim3(H_DIM / 32, CAT / 32),    tb>>>(W1,      CAT,    H_DIM,  W12h);
    whalf<<<dim3(H_DIM / 32, CAT / 32),    tb>>>(W2,      CAT,    H_DIM,  W12h + (size_t)H_DIM * CAT);
    whalf<<<dim3(H_DIM / 32, CAT / 32),    tb>>>(W3,      CAT,    H_DIM,  W3h);
    whalf<<<dim3(H_DIM / 32, IN_DIM / 32), tb>>>(W_belta, IN_DIM, H_DIM,  Wbh);
    whalf<<<dim3(IN_DIM / 32, H_DIM / 32), tb>>>(W_out,   H_DIM,  IN_DIM, Woh);
    whalf<<<dim3(IN_DIM / 32, ZDIM / 32),  tb>>>(W_z,     ZDIM,   IN_DIM, Wzh);

    const dim3 blk(256);
    const dim3 gridH (H_DIM / 128,  B_DIM / 128);   // (8, 32)
    const dim3 gridH2(N12 / 128,    B_DIM / 128);   // (16, 32)
    const dim3 gridI (IN_DIM / 128, B_DIM / 128);   // (4, 32)

    // x0 = z @ W_z + b_z  -> x fp16 only
    tgemm<EPI_LIN><<<gridI, blk, SMEM_T>>>(zh, ZDIM, ZDIM, nullptr, 0, 0,
                                           Wzh, b_z, nullptr, nullptr, nullptr,
                                           nullptr, 0, xh, IN_DIM);

    for (int t = 0; t < SEQ_LEN; t++) {
        // spre = exp(-relu(td_t @ W_belta + b)) * state   (fp32 + fp16)
        tgemm<EPI_BELTA><<<gridH, blk, SMEM_T>>>(tdh + (size_t)t * IN_DIM, LDO, IN_DIM,
                                                 nullptr, 0, 0,
                                                 Wbh, b_belta, nullptr, stf, nullptr,
                                                 spf, H_DIM, sph, H_DIM);
        // fused: u = sig([spre|x]W1+b1) -> uf ;  rs = sig([spre|x]W2+b2)*spre -> fp16
        tgemm<EPI_SIGUR><<<gridH2, blk, SMEM_T>>>(sph, H_DIM, H_DIM,
                                                  xh, IN_DIM, IN_DIM,
                                                  W12h, b1, b2, spf, nullptr,
                                                  uf, H_DIM, rsh, H_DIM);
        // state = (1-u)*spre + u*tanh([rs|x] @ W3 + b3)   (fp32 + fp16)
        tgemm<EPI_NEW><<<gridH, blk, SMEM_T>>>(rsh, H_DIM, H_DIM,
                                               xh, IN_DIM, IN_DIM,
                                               W3h, b3, nullptr, uf, spf,
                                               stf, H_DIM, sth, H_DIM);
        // out_t = state @ W_out + b_out  (fp32 strided into d_out + x fp16 feedback)
        tgemm<EPI_LIN><<<gridI, blk, SMEM_T>>>(sth, H_DIM, H_DIM,
                                               nullptr, 0, 0,
                                               Woh, b_out, nullptr, nullptr, nullptr,
                                               out + (size_t)t * IN_DIM, LDO,
                                               xh, IN_DIM);
    }
}